// round 3
// baseline (speedup 1.0000x reference)
#include <cuda_runtime.h>
#include <cuda_bf16.h>
#include <mma.h>
#include <cstdint>

using namespace nvcuda;

#define DINL __device__ __forceinline__
constexpr int B_ = 128, L_ = 4, VT_ = 50000, E_ = 256, H_ = 512, OOV_ = 50;
constexpr int VTOT = VT_ + OOV_, NPAD = 50048, NT = 782;

__device__ float g_xh[B_ * 768];
__device__ float g_gates[B_ * 2048];
__device__ float g_dec[B_ * H_];
__device__ __nv_bfloat16 g_dec_bf[B_ * H_];
__device__ float g_d1[B_ * H_], g_d2[B_ * H_];
__device__ float g_part_acc[1024 * H_], g_part_m[1024], g_part_s[1024];
__device__ float g_scores2[B_ * 1024], g_m2[B_], g_s2[B_];
__device__ float g_ctx[B_ * H_], g_cctx[B_ * H_], g_pgen[B_];
__device__ float g_logits[(size_t)B_ * NPAD];
__device__ float g_rowm[B_], g_rows[B_];
__device__ float g_copy[(size_t)B_ * VTOT];

DINL float sigf(float x) { return 1.0f / (1.0f + __expf(-x)); }

// ---- embed + pack [x|h0] : 128 blocks x 768 ----
__global__ void k_embed(const int* __restrict__ ids, const float* __restrict__ emb,
                        const float* __restrict__ h0) {
    int b = blockIdx.x, t = threadIdx.x;
    if (t < 256) {
        float s = 0.f;
        #pragma unroll
        for (int l = 0; l < L_; l++) s += emb[(size_t)ids[b * L_ + l] * E_ + t];
        g_xh[b * 768 + t] = tanhf(s * 0.25f);
    } else g_xh[b * 768 + t] = h0[b * H_ + t - 256];
}

// ---- generic C[128,N] (+)= A[128,K] @ W[N,K]^T (+bias). grid=N/16, 256 thr ----
__global__ void k_gemm128(int mode, const float* __restrict__ W, const float* __restrict__ bias) {
    float* C; const float* A; int lda, K, beta, ldc;
    if (mode == 0)      { C = g_gates; A = g_xh;       lda = 768; K = 256; beta = 0; ldc = 2048; }
    else if (mode == 1) { C = g_gates; A = g_xh + 256; lda = 768; K = 512; beta = 1; ldc = 2048; }
    else if (mode == 2) { C = g_d1;    A = g_dec;      lda = 512; K = 512; beta = 0; ldc = 512; }
    else                { C = g_d2;    A = g_dec;      lda = 512; K = 512; beta = 0; ldc = 512; }
    __shared__ float As[128][33], Ws[16][33];
    int tid = threadIdx.x, j0 = blockIdx.x * 16, tx = tid & 7, ty = tid >> 3;
    float acc[4][2] = {};
    for (int k0 = 0; k0 < K; k0 += 32) {
        #pragma unroll
        for (int i = 0; i < 16; i++) {
            int f = tid + i * 256;
            As[f >> 5][f & 31] = A[(f >> 5) * lda + k0 + (f & 31)];
        }
        #pragma unroll
        for (int i = 0; i < 2; i++) {
            int f = tid + i * 256;
            Ws[f >> 5][f & 31] = W[(j0 + (f >> 5)) * K + k0 + (f & 31)];
        }
        __syncthreads();
        #pragma unroll
        for (int kk = 0; kk < 32; kk++) {
            float w0 = Ws[tx * 2][kk], w1 = Ws[tx * 2 + 1][kk];
            #pragma unroll
            for (int i = 0; i < 4; i++) {
                float a = As[ty * 4 + i][kk];
                acc[i][0] += a * w0; acc[i][1] += a * w1;
            }
        }
        __syncthreads();
    }
    #pragma unroll
    for (int i = 0; i < 4; i++)
        #pragma unroll
        for (int j = 0; j < 2; j++) {
            int bb = ty * 4 + i, jj = j0 + tx * 2 + j;
            float v = acc[i][j] + (bias ? bias[jj] : 0.f);
            if (beta) C[bb * ldc + jj] += v; else C[bb * ldc + jj] = v;
        }
}

// ---- LSTM epilogue: 128 x 512 ----
__global__ void k_lstm(const float* __restrict__ b_ih, const float* __restrict__ b_hh,
                       const float* __restrict__ c0, float* __restrict__ out) {
    int b = blockIdx.x, j = threadIdx.x;
    const float* gr = g_gates + b * 2048;
    float gi = gr[j] + b_ih[j] + b_hh[j];
    float gf = gr[j + 512] + b_ih[j + 512] + b_hh[j + 512];
    float gg = gr[j + 1024] + b_ih[j + 1024] + b_hh[j + 1024];
    float go = gr[j + 1536] + b_ih[j + 1536] + b_hh[j + 1536];
    float c = sigf(gf) * c0[b * H_ + j] + sigf(gi) * tanhf(gg);
    float h = sigf(go) * tanhf(c);
    g_dec[b * H_ + j] = h;
    g_dec_bf[b * H_ + j] = __float2bfloat16(h);
    out[(size_t)B_ * VTOT + b * H_ + j] = h;
    out[(size_t)B_ * VTOT + B_ * H_ + b * H_ + j] = c;
}

// ---- fused online-softmax attention partials: 1024 blocks x 256 ----
__global__ void k_attn(const float* __restrict__ enc1, const float* __restrict__ enc2) {
    __shared__ float s_d[512];
    __shared__ __align__(16) float s_tile[16 * 512];
    __shared__ float s_sc[16], s_p[16];
    int cta = blockIdx.x, seg = cta & 3, row = cta >> 2, attn = row >> 7, b = row & 127;
    const float* enc = (attn ? enc2 : enc1) + (size_t)b * 1024 * 512;
    const float* dv = (attn ? g_d2 : g_d1) + b * 512;
    int tid = threadIdx.x, wid = tid >> 5, lane = tid & 31;
    for (int i = tid; i < 512; i += 256) s_d[i] = dv[i];
    float m = -1e30f, s = 0.f, acc0 = 0.f, acc1 = 0.f;
    __syncthreads();
    for (int tile = 0; tile < 16; tile++) {
        int t0 = seg * 256 + tile * 16;
        const float4* src = (const float4*)(enc + (size_t)t0 * 512);
        #pragma unroll
        for (int i = 0; i < 8; i++) ((float4*)s_tile)[tid + i * 256] = src[tid + i * 256];
        __syncthreads();
        #pragma unroll
        for (int jj = 0; jj < 2; jj++) {
            int j = wid * 2 + jj;
            float p = 0.f;
            #pragma unroll
            for (int i = 0; i < 16; i++) p += s_tile[j * 512 + lane + i * 32] * s_d[lane + i * 32];
            #pragma unroll
            for (int off = 16; off; off >>= 1) p += __shfl_xor_sync(0xFFFFFFFFu, p, off);
            if (lane == 0) {
                s_sc[j] = p;
                if (attn) g_scores2[b * 1024 + t0 + j] = p;
            }
        }
        __syncthreads();
        float tmax = s_sc[0];
        #pragma unroll
        for (int j = 1; j < 16; j++) tmax = fmaxf(tmax, s_sc[j]);
        float newm = fmaxf(m, tmax);
        if (tid < 16) s_p[tid] = __expf(s_sc[tid] - newm);
        __syncthreads();
        float scale = __expf(m - newm);
        acc0 *= scale; acc1 *= scale;
        float psum = 0.f;
        #pragma unroll
        for (int j = 0; j < 16; j++) {
            float p = s_p[j];
            psum += p;
            acc0 += p * s_tile[j * 512 + tid];
            acc1 += p * s_tile[j * 512 + tid + 256];
        }
        s = s * scale + psum; m = newm;
        __syncthreads();
    }
    float* pa = g_part_acc + (size_t)cta * 512;
    pa[tid] = acc0; pa[tid + 256] = acc1;
    if (tid == 0) { g_part_m[cta] = m; g_part_s[cta] = s; }
}

// ---- combine 4 segments: 256 x 512 ----
__global__ void k_combine() {
    int row = blockIdx.x, h = threadIdx.x;
    float m0 = g_part_m[row * 4], m1 = g_part_m[row * 4 + 1];
    float m2 = g_part_m[row * 4 + 2], m3 = g_part_m[row * 4 + 3];
    float M = fmaxf(fmaxf(m0, m1), fmaxf(m2, m3));
    float w0 = __expf(m0 - M), w1 = __expf(m1 - M), w2 = __expf(m2 - M), w3 = __expf(m3 - M);
    float S = g_part_s[row * 4] * w0 + g_part_s[row * 4 + 1] * w1 +
              g_part_s[row * 4 + 2] * w2 + g_part_s[row * 4 + 3] * w3;
    float a = g_part_acc[(size_t)(row * 4) * 512 + h] * w0 +
              g_part_acc[(size_t)(row * 4 + 1) * 512 + h] * w1 +
              g_part_acc[(size_t)(row * 4 + 2) * 512 + h] * w2 +
              g_part_acc[(size_t)(row * 4 + 3) * 512 + h] * w3;
    float v = a / S;
    if (row < 128) g_ctx[row * 512 + h] = v;
    else {
        g_cctx[(row - 128) * 512 + h] = v;
        if (h == 0) { g_m2[row - 128] = M; g_s2[row - 128] = S; }
    }
}

// ---- p_gen: 128 x 256 ----
__global__ void k_pgen(const float* __restrict__ gen_W, const float* __restrict__ gen_b,
                       const float* __restrict__ sig_b, const int* __restrict__ ci) {
    __shared__ float red[256];
    __shared__ int redc[256];
    int b = blockIdx.x, tid = threadIdx.x;
    float part = 0.f;
    for (int i = tid; i < 1792; i += 256) {
        float fv;
        if (i < 512) fv = g_ctx[b * 512 + i];
        else if (i < 1024) fv = g_cctx[b * 512 + i - 512];
        else if (i < 1536) fv = g_dec[b * 512 + i - 1024];
        else fv = g_xh[b * 768 + i - 1536];
        part += fv * gen_W[i];
    }
    int cnt = 0;
    for (int t = tid; t < 1024; t += 256) cnt += (ci[b * 1024 + t] > 0);
    red[tid] = part; redc[tid] = cnt;
    __syncthreads();
    for (int st = 128; st; st >>= 1) {
        if (tid < st) { red[tid] += red[tid + st]; redc[tid] += redc[tid + st]; }
        __syncthreads();
    }
    if (tid == 0) g_pgen[b] = (redc[0] == 0) ? 1.0f : sigf(red[0] + gen_b[0] + sig_b[0]);
}

__global__ void k_zero() {
    size_t i = (size_t)blockIdx.x * 256 + threadIdx.x;
    if (i < ((size_t)B_ * VTOT) / 4) ((float4*)g_copy)[i] = make_float4(0.f, 0.f, 0.f, 0.f);
}

__global__ void k_scatter(const int* __restrict__ ci) {
    int idx = blockIdx.x * 256 + threadIdx.x;
    int b = idx >> 10, t = idx & 1023;
    float p = __expf(g_scores2[b * 1024 + t] - g_m2[b]) / g_s2[b];
    atomicAdd(&g_copy[(size_t)b * VTOT + ci[b * 1024 + t]], p);
}

// ---- vocab projection: wmma bf16, 128x64 tile per CTA, K=512. 782 x 256 ----
__global__ void __launch_bounds__(256) k_proj(const float* __restrict__ out_W,
                                              const float* __restrict__ out_b) {
    __shared__ __align__(16) __nv_bfloat16 As[128][64];   // 16 KB
    __shared__ __align__(16) __nv_bfloat16 Bs[64][64];    //  8 KB
    __shared__ __align__(16) float BiasS[16][64];         //  4 KB
    int tid = threadIdx.x, wid = tid >> 5;
    int v0 = blockIdx.x * 64;
    int wr = wid >> 1, wc = wid & 1;   // warp tile: rows [wr*32,+32), cols [wc*32,+32)

    // bias tile (replicated over 16 rows so it can seed the accumulator frag)
    {
        int c = tid & 63, r4 = tid >> 6;   // 4 rows per pass
        int v = v0 + c;
        float bv = (v < VT_) ? out_b[v] : 0.f;
        #pragma unroll
        for (int rr = 0; rr < 4; rr++) BiasS[r4 * 4 + rr][c] = bv;
    }
    __syncthreads();

    wmma::fragment<wmma::accumulator, 16, 16, 16, float> c_frag[2][2];
    #pragma unroll
    for (int i = 0; i < 2; i++)
        #pragma unroll
        for (int j = 0; j < 2; j++)
            wmma::load_matrix_sync(c_frag[i][j], &BiasS[0][wc * 32 + j * 16], 64,
                                   wmma::mem_row_major);

    const uint32_t* decw = (const uint32_t*)g_dec_bf;     // 128 rows x 256 words
    for (int kc = 0; kc < 8; kc++) {
        #pragma unroll
        for (int i = 0; i < 16; i++) {      // A: 128 rows x 32 words
            int f = tid + i * 256, r = f >> 5, c = f & 31;
            ((uint32_t*)&As[r][0])[c] = decw[r * 256 + kc * 32 + c];
        }
        #pragma unroll
        for (int i = 0; i < 8; i++) {       // B: 64 rows x 32 float2 -> bf16x2
            int f = tid + i * 256, r = f >> 5, c = f & 31;
            int v = v0 + r;
            float2 w2 = (v < VT_) ? ((const float2*)(out_W + (size_t)v * 512 + kc * 64))[c]
                                  : make_float2(0.f, 0.f);
            __nv_bfloat162 bb = __floats2bfloat162_rn(w2.x, w2.y);
            ((uint32_t*)&Bs[r][0])[c] = *(uint32_t*)&bb;
        }
        __syncthreads();
        #pragma unroll
        for (int kk = 0; kk < 64; kk += 16) {
            wmma::fragment<wmma::matrix_a, 16, 16, 16, __nv_bfloat16, wmma::row_major> a_frag[2];
            wmma::fragment<wmma::matrix_b, 16, 16, 16, __nv_bfloat16, wmma::col_major> b_frag[2];
            #pragma unroll
            for (int i = 0; i < 2; i++)
                wmma::load_matrix_sync(a_frag[i], &As[wr * 32 + i * 16][kk], 64);
            #pragma unroll
            for (int j = 0; j < 2; j++)
                wmma::load_matrix_sync(b_frag[j], &Bs[wc * 32 + j * 16][kk], 64);
            #pragma unroll
            for (int i = 0; i < 2; i++)
                #pragma unroll
                for (int j = 0; j < 2; j++)
                    wmma::mma_sync(c_frag[i][j], a_frag[i], b_frag[j], c_frag[i][j]);
        }
        __syncthreads();
    }
    // store straight to padded logits (cols >= VT_ land in pad area, never read)
    #pragma unroll
    for (int i = 0; i < 2; i++)
        #pragma unroll
        for (int j = 0; j < 2; j++)
            wmma::store_matrix_sync(
                g_logits + (size_t)(wr * 32 + i * 16) * NPAD + v0 + wc * 32 + j * 16,
                c_frag[i][j], NPAD, wmma::mem_row_major);
}

// ---- row softmax stats: 128 x 1024 ----
__global__ void k_rowstat() {
    __shared__ float rm[1024], rs[1024];
    int b = blockIdx.x, tid = threadIdx.x;
    float m = -1e30f, s = 0.f;
    for (int v = tid; v < VT_; v += 1024) {
        float x = g_logits[(size_t)b * NPAD + v];
        if (x > m) { s = s * __expf(m - x) + 1.f; m = x; }
        else s += __expf(x - m);
    }
    rm[tid] = m; rs[tid] = s;
    __syncthreads();
    for (int st = 512; st; st >>= 1) {
        if (tid < st) {
            float m1 = rm[tid], s1 = rs[tid], m2 = rm[tid + st], s2 = rs[tid + st];
            float M = fmaxf(m1, m2);
            rm[tid] = M;
            rs[tid] = s1 * __expf(m1 - M) + s2 * __expf(m2 - M);
        }
        __syncthreads();
    }
    if (tid == 0) { g_rowm[b] = rm[0]; g_rows[b] = rs[0]; }
}

// ---- final: grid (196, 128) x 256 ----
__global__ void k_final(float* __restrict__ out) {
    int b = blockIdx.y, v = blockIdx.x * 256 + threadIdx.x;
    if (v >= VTOT) return;
    float pg = g_pgen[b];
    float pv = (v < VT_) ? __expf(g_logits[(size_t)b * NPAD + v] - g_rowm[b]) / g_rows[b] : 0.f;
    float pc = g_copy[(size_t)b * VTOT + v];
    out[(size_t)b * VTOT + v] = logf(fmaxf(pg * pv + (1.f - pg) * pc, 1e-10f));
}

extern "C" void kernel_launch(void* const* d_in, const int* in_sizes, int n_in,
                              void* d_out, int out_size) {
    const int*   ids    = (const int*)d_in[0];
    const float* h0     = (const float*)d_in[1];
    const float* c0     = (const float*)d_in[2];
    const float* enc    = (const float*)d_in[3];
    const float* cenc   = (const float*)d_in[4];
    const int*   ci     = (const int*)d_in[5];
    const float* emb    = (const float*)d_in[6];
    const float* W_ih   = (const float*)d_in[7];
    const float* W_hh   = (const float*)d_in[8];
    const float* b_ih   = (const float*)d_in[9];
    const float* b_hh   = (const float*)d_in[10];
    const float* attn_W = (const float*)d_in[11];
    const float* attn_b = (const float*)d_in[12];
    const float* cattn_W = (const float*)d_in[13];
    const float* cattn_b = (const float*)d_in[14];
    const float* gen_W  = (const float*)d_in[15];
    const float* gen_b  = (const float*)d_in[16];
    const float* sig_b  = (const float*)d_in[17];
    const float* out_W  = (const float*)d_in[18];
    const float* out_b  = (const float*)d_in[19];
    float* out = (float*)d_out;

    k_embed<<<128, 768>>>(ids, emb, h0);
    k_gemm128<<<128, 256>>>(0, W_ih, nullptr);
    k_gemm128<<<128, 256>>>(1, W_hh, nullptr);
    k_lstm<<<128, 512>>>(b_ih, b_hh, c0, out);
    k_gemm128<<<32, 256>>>(2, attn_W, attn_b);
    k_gemm128<<<32, 256>>>(3, cattn_W, cattn_b);
    k_zero<<<6257, 256>>>();
    k_attn<<<1024, 256>>>(enc, cenc);
    k_combine<<<256, 512>>>();
    k_pgen<<<128, 256>>>(gen_W, gen_b, sig_b, ci);
    k_scatter<<<512, 256>>>(ci);
    k_proj<<<NT, 256>>>(out_W, out_b);
    k_rowstat<<<128, 1024>>>();
    k_final<<<dim3(196, 128), 256>>>(out);
}

// round 8
// speedup vs baseline: 1.5195x; 1.5195x over previous
#include <cuda_runtime.h>
#include <cuda_bf16.h>
#include <mma.h>
#include <cstdint>

using namespace nvcuda;

#define DINL __device__ __forceinline__
constexpr int B_ = 128, L_ = 4, VT_ = 50000, E_ = 256, H_ = 512, OOV_ = 50;
constexpr int VTOT = VT_ + OOV_, NPAD = 50048, NT = 782;

__device__ float g_xh[B_ * 768];
__device__ float g_gates[B_ * 2048];
__device__ float g_dec[B_ * H_];
__device__ __nv_bfloat16 g_dec_bf[B_ * H_];
__device__ float g_d1[B_ * H_], g_d2[B_ * H_];
__device__ float g_part_acc[1024 * H_], g_part_m[1024], g_part_s[1024];
__device__ float g_scores2[B_ * 1024], g_m2[B_], g_s2[B_];
__device__ float g_ctx[B_ * H_], g_cctx[B_ * H_], g_pgen[B_];
__device__ float g_logits[(size_t)B_ * NPAD];
__device__ float g_rowm[B_], g_rows[B_];
__device__ float g_copy[(size_t)B_ * VTOT];

DINL float sigf(float x) { return 1.0f / (1.0f + __expf(-x)); }

// ---- embed + pack [x|h0] : 128 blocks x 768 ----
__global__ void k_embed(const int* __restrict__ ids, const float* __restrict__ emb,
                        const float* __restrict__ h0) {
    int b = blockIdx.x, t = threadIdx.x;
    if (t < 256) {
        float s = 0.f;
        #pragma unroll
        for (int l = 0; l < L_; l++) s += emb[(size_t)ids[b * L_ + l] * E_ + t];
        g_xh[b * 768 + t] = tanhf(s * 0.25f);
    } else g_xh[b * 768 + t] = h0[b * H_ + t - 256];
}

// ---- fused gates GEMM: g_gates[128,2048] = xh[128,768] @ [W_ih|W_hh]^T. grid=128 ----
__global__ void k_gates(const float* __restrict__ W_ih, const float* __restrict__ W_hh) {
    __shared__ float As[128][33], Ws[16][33];
    int tid = threadIdx.x, j0 = blockIdx.x * 16, tx = tid & 7, ty = tid >> 3;
    float acc[4][2] = {};
    for (int k0 = 0; k0 < 768; k0 += 32) {
        #pragma unroll
        for (int i = 0; i < 16; i++) {
            int f = tid + i * 256;
            As[f >> 5][f & 31] = g_xh[(f >> 5) * 768 + k0 + (f & 31)];
        }
        #pragma unroll
        for (int i = 0; i < 2; i++) {
            int f = tid + i * 256, jj = j0 + (f >> 5), kk = k0 + (f & 31);
            Ws[f >> 5][f & 31] = (kk < 256) ? W_ih[jj * 256 + kk] : W_hh[jj * 512 + kk - 256];
        }
        __syncthreads();
        #pragma unroll
        for (int kk = 0; kk < 32; kk++) {
            float w0 = Ws[tx * 2][kk], w1 = Ws[tx * 2 + 1][kk];
            #pragma unroll
            for (int i = 0; i < 4; i++) {
                float a = As[ty * 4 + i][kk];
                acc[i][0] += a * w0; acc[i][1] += a * w1;
            }
        }
        __syncthreads();
    }
    #pragma unroll
    for (int i = 0; i < 4; i++)
        #pragma unroll
        for (int j = 0; j < 2; j++)
            g_gates[(ty * 4 + i) * 2048 + j0 + tx * 2 + j] = acc[i][j];
}

// ---- d1/d2 projections: grid (32,2) ----
__global__ void k_dproj(const float* __restrict__ attn_W, const float* __restrict__ attn_b,
                        const float* __restrict__ cattn_W, const float* __restrict__ cattn_b) {
    const float* W = blockIdx.y ? cattn_W : attn_W;
    const float* bias = blockIdx.y ? cattn_b : attn_b;
    float* C = blockIdx.y ? g_d2 : g_d1;
    __shared__ float As[128][33], Ws[16][33];
    int tid = threadIdx.x, j0 = blockIdx.x * 16, tx = tid & 7, ty = tid >> 3;
    float acc[4][2] = {};
    for (int k0 = 0; k0 < 512; k0 += 32) {
        #pragma unroll
        for (int i = 0; i < 16; i++) {
            int f = tid + i * 256;
            As[f >> 5][f & 31] = g_dec[(f >> 5) * 512 + k0 + (f & 31)];
        }
        #pragma unroll
        for (int i = 0; i < 2; i++) {
            int f = tid + i * 256;
            Ws[f >> 5][f & 31] = W[(j0 + (f >> 5)) * 512 + k0 + (f & 31)];
        }
        __syncthreads();
        #pragma unroll
        for (int kk = 0; kk < 32; kk++) {
            float w0 = Ws[tx * 2][kk], w1 = Ws[tx * 2 + 1][kk];
            #pragma unroll
            for (int i = 0; i < 4; i++) {
                float a = As[ty * 4 + i][kk];
                acc[i][0] += a * w0; acc[i][1] += a * w1;
            }
        }
        __syncthreads();
    }
    #pragma unroll
    for (int i = 0; i < 4; i++)
        #pragma unroll
        for (int j = 0; j < 2; j++) {
            int jj = j0 + tx * 2 + j;
            C[(ty * 4 + i) * 512 + jj] = acc[i][j] + bias[jj];
        }
}

// ---- LSTM epilogue: 128 x 512 ----
__global__ void k_lstm(const float* __restrict__ b_ih, const float* __restrict__ b_hh,
                       const float* __restrict__ c0, float* __restrict__ out) {
    int b = blockIdx.x, j = threadIdx.x;
    const float* gr = g_gates + b * 2048;
    float gi = gr[j] + b_ih[j] + b_hh[j];
    float gf = gr[j + 512] + b_ih[j + 512] + b_hh[j + 512];
    float gg = gr[j + 1024] + b_ih[j + 1024] + b_hh[j + 1024];
    float go = gr[j + 1536] + b_ih[j + 1536] + b_hh[j + 1536];
    float c = sigf(gf) * c0[b * H_ + j] + sigf(gi) * tanhf(gg);
    float h = sigf(go) * tanhf(c);
    g_dec[b * H_ + j] = h;
    g_dec_bf[b * H_ + j] = __float2bfloat16(h);
    out[(size_t)B_ * VTOT + b * H_ + j] = h;
    out[(size_t)B_ * VTOT + B_ * H_ + b * H_ + j] = c;
}

// ---- attention: per-warp independent online softmax, all-register mainloop ----
// grid 1024 = ((attn*128+b)*4+seg), 256 thr. Warp w owns rows {2w,2w+1} of each 16-row tile.
__global__ void __launch_bounds__(256) k_attn(const float* __restrict__ enc1,
                                              const float* __restrict__ enc2) {
    __shared__ float s_acc[8][512];
    __shared__ float s_m[8], s_s[8];
    int cta = blockIdx.x, seg = cta & 3, row = cta >> 2, attn = row >> 7, b = row & 127;
    const float* enc = (attn ? enc2 : enc1) + (size_t)b * 1024 * 512;
    const float* dv = (attn ? g_d2 : g_d1) + b * 512;
    int tid = threadIdx.x, wid = tid >> 5, lane = tid & 31;
    float4 d4[4];
    #pragma unroll
    for (int k = 0; k < 4; k++) d4[k] = ((const float4*)dv)[lane + 32 * k];
    float m = -1e30f, s = 0.f;
    float4 a4[4] = {};
    for (int tile = 0; tile < 16; tile++) {
        int r0 = seg * 256 + tile * 16 + 2 * wid;
        const float4* p0 = (const float4*)(enc + (size_t)r0 * 512);
        float4 v0[4], v1[4];
        #pragma unroll
        for (int k = 0; k < 4; k++) { v0[k] = p0[lane + 32 * k]; v1[k] = p0[128 + lane + 32 * k]; }
        float dot0 = 0.f, dot1 = 0.f;
        #pragma unroll
        for (int k = 0; k < 4; k++) {
            dot0 += v0[k].x * d4[k].x + v0[k].y * d4[k].y + v0[k].z * d4[k].z + v0[k].w * d4[k].w;
            dot1 += v1[k].x * d4[k].x + v1[k].y * d4[k].y + v1[k].z * d4[k].z + v1[k].w * d4[k].w;
        }
        #pragma unroll
        for (int off = 16; off; off >>= 1) {
            dot0 += __shfl_xor_sync(0xFFFFFFFFu, dot0, off);
            dot1 += __shfl_xor_sync(0xFFFFFFFFu, dot1, off);
        }
        if (attn && lane == 0) {
            g_scores2[b * 1024 + r0] = dot0;
            g_scores2[b * 1024 + r0 + 1] = dot1;
        }
        float nm = fmaxf(m, fmaxf(dot0, dot1));
        float sc = __expf(m - nm);
        float p0e = __expf(dot0 - nm), p1e = __expf(dot1 - nm);
        s = s * sc + p0e + p1e;
        #pragma unroll
        for (int k = 0; k < 4; k++) {
            a4[k].x = a4[k].x * sc + p0e * v0[k].x + p1e * v1[k].x;
            a4[k].y = a4[k].y * sc + p0e * v0[k].y + p1e * v1[k].y;
            a4[k].z = a4[k].z * sc + p0e * v0[k].z + p1e * v1[k].z;
            a4[k].w = a4[k].w * sc + p0e * v0[k].w + p1e * v1[k].w;
        }
        m = nm;
    }
    #pragma unroll
    for (int k = 0; k < 4; k++) ((float4*)s_acc[wid])[lane + 32 * k] = a4[k];
    if (lane == 0) { s_m[wid] = m; s_s[wid] = s; }
    __syncthreads();
    float M = s_m[0];
    #pragma unroll
    for (int w = 1; w < 8; w++) M = fmaxf(M, s_m[w]);
    float S = 0.f, acc0 = 0.f, acc1 = 0.f;
    #pragma unroll
    for (int w = 0; w < 8; w++) {
        float f = __expf(s_m[w] - M);
        S += f * s_s[w];
        acc0 += f * s_acc[w][tid];
        acc1 += f * s_acc[w][tid + 256];
    }
    float* pa = g_part_acc + (size_t)cta * 512;
    pa[tid] = acc0; pa[tid + 256] = acc1;
    if (tid == 0) { g_part_m[cta] = M; g_part_s[cta] = S; }
}

// ---- combine 4 segments: 256 x 512 ----
__global__ void k_combine() {
    int row = blockIdx.x, h = threadIdx.x;
    float m0 = g_part_m[row * 4], m1 = g_part_m[row * 4 + 1];
    float m2 = g_part_m[row * 4 + 2], m3 = g_part_m[row * 4 + 3];
    float M = fmaxf(fmaxf(m0, m1), fmaxf(m2, m3));
    float w0 = __expf(m0 - M), w1 = __expf(m1 - M), w2 = __expf(m2 - M), w3 = __expf(m3 - M);
    float S = g_part_s[row * 4] * w0 + g_part_s[row * 4 + 1] * w1 +
              g_part_s[row * 4 + 2] * w2 + g_part_s[row * 4 + 3] * w3;
    float a = g_part_acc[(size_t)(row * 4) * 512 + h] * w0 +
              g_part_acc[(size_t)(row * 4 + 1) * 512 + h] * w1 +
              g_part_acc[(size_t)(row * 4 + 2) * 512 + h] * w2 +
              g_part_acc[(size_t)(row * 4 + 3) * 512 + h] * w3;
    float v = a / S;
    if (row < 128) g_ctx[row * 512 + h] = v;
    else {
        g_cctx[(row - 128) * 512 + h] = v;
        if (h == 0) { g_m2[row - 128] = M; g_s2[row - 128] = S; }
    }
}

// ---- p_gen: 128 x 256 ----
__global__ void k_pgen(const float* __restrict__ gen_W, const float* __restrict__ gen_b,
                       const float* __restrict__ sig_b, const int* __restrict__ ci) {
    __shared__ float red[256];
    __shared__ int redc[256];
    int b = blockIdx.x, tid = threadIdx.x;
    float part = 0.f;
    for (int i = tid; i < 1792; i += 256) {
        float fv;
        if (i < 512) fv = g_ctx[b * 512 + i];
        else if (i < 1024) fv = g_cctx[b * 512 + i - 512];
        else if (i < 1536) fv = g_dec[b * 512 + i - 1024];
        else fv = g_xh[b * 768 + i - 1536];
        part += fv * gen_W[i];
    }
    int cnt = 0;
    for (int t = tid; t < 1024; t += 256) cnt += (ci[b * 1024 + t] > 0);
    red[tid] = part; redc[tid] = cnt;
    __syncthreads();
    for (int st = 128; st; st >>= 1) {
        if (tid < st) { red[tid] += red[tid + st]; redc[tid] += redc[tid + st]; }
        __syncthreads();
    }
    if (tid == 0) g_pgen[b] = (redc[0] == 0) ? 1.0f : sigf(red[0] + gen_b[0] + sig_b[0]);
}

__global__ void k_zero() {
    size_t i = (size_t)blockIdx.x * 256 + threadIdx.x;
    if (i < ((size_t)B_ * VTOT) / 4) ((float4*)g_copy)[i] = make_float4(0.f, 0.f, 0.f, 0.f);
}

__global__ void k_scatter(const int* __restrict__ ci) {
    int idx = blockIdx.x * 256 + threadIdx.x;
    int b = idx >> 10, t = idx & 1023;
    float p = __expf(g_scores2[b * 1024 + t] - g_m2[b]) / g_s2[b];
    atomicAdd(&g_copy[(size_t)b * VTOT + ci[b * 1024 + t]], p);
}

// ---- vocab projection: wmma bf16, 128x64 per CTA, padded smem (stride 72). 782 x 256 ----
__global__ void __launch_bounds__(256) k_proj(const float* __restrict__ out_W,
                                              const float* __restrict__ out_b) {
    __shared__ __align__(16) __nv_bfloat16 As[128][72];   // 18 KB, rows staggered 4 banks
    __shared__ __align__(16) __nv_bfloat16 Bs[64][72];    //  9 KB
    __shared__ __align__(16) float BiasS[16][64];         //  4 KB
    int tid = threadIdx.x, wid = tid >> 5;
    int v0 = blockIdx.x * 64;
    int wr = wid >> 1, wc = wid & 1;
    {
        int c = tid & 63, r4 = tid >> 6;
        int v = v0 + c;
        float bv = (v < VT_) ? out_b[v] : 0.f;
        #pragma unroll
        for (int rr = 0; rr < 4; rr++) BiasS[r4 * 4 + rr][c] = bv;
    }
    __syncthreads();
    wmma::fragment<wmma::accumulator, 16, 16, 16, float> c_frag[2][2];
    #pragma unroll
    for (int i = 0; i < 2; i++)
        #pragma unroll
        for (int j = 0; j < 2; j++)
            wmma::load_matrix_sync(c_frag[i][j], &BiasS[0][wc * 32 + j * 16], 64,
                                   wmma::mem_row_major);
    const uint32_t* decw = (const uint32_t*)g_dec_bf;
    for (int kc = 0; kc < 8; kc++) {
        #pragma unroll
        for (int i = 0; i < 16; i++) {
            int f = tid + i * 256, r = f >> 5, c = f & 31;
            ((uint32_t*)&As[r][0])[c] = decw[r * 256 + kc * 32 + c];
        }
        #pragma unroll
        for (int i = 0; i < 8; i++) {
            int f = tid + i * 256, r = f >> 5, c = f & 31;
            int v = v0 + r;
            float2 w2 = (v < VT_) ? ((const float2*)(out_W + (size_t)v * 512 + kc * 64))[c]
                                  : make_float2(0.f, 0.f);
            __nv_bfloat162 bb = __floats2bfloat162_rn(w2.x, w2.y);
            ((uint32_t*)&Bs[r][0])[c] = *(uint32_t*)&bb;
        }
        __syncthreads();
        #pragma unroll
        for (int kk = 0; kk < 64; kk += 16) {
            wmma::fragment<wmma::matrix_a, 16, 16, 16, __nv_bfloat16, wmma::row_major> a_frag[2];
            wmma::fragment<wmma::matrix_b, 16, 16, 16, __nv_bfloat16, wmma::col_major> b_frag[2];
            #pragma unroll
            for (int i = 0; i < 2; i++)
                wmma::load_matrix_sync(a_frag[i], &As[wr * 32 + i * 16][kk], 72);
            #pragma unroll
            for (int j = 0; j < 2; j++)
                wmma::load_matrix_sync(b_frag[j], &Bs[wc * 32 + j * 16][kk], 72);
            #pragma unroll
            for (int i = 0; i < 2; i++)
                #pragma unroll
                for (int j = 0; j < 2; j++)
                    wmma::mma_sync(c_frag[i][j], a_frag[i], b_frag[j], c_frag[i][j]);
        }
        __syncthreads();
    }
    #pragma unroll
    for (int i = 0; i < 2; i++)
        #pragma unroll
        for (int j = 0; j < 2; j++)
            wmma::store_matrix_sync(
                g_logits + (size_t)(wr * 32 + i * 16) * NPAD + v0 + wc * 32 + j * 16,
                c_frag[i][j], NPAD, wmma::mem_row_major);
}

// ---- row softmax stats: 128 x 1024 ----
__global__ void k_rowstat() {
    __shared__ float rm[1024], rs[1024];
    int b = blockIdx.x, tid = threadIdx.x;
    float m = -1e30f, s = 0.f;
    for (int v = tid; v < VT_; v += 1024) {
        float x = g_logits[(size_t)b * NPAD + v];
        if (x > m) { s = s * __expf(m - x) + 1.f; m = x; }
        else s += __expf(x - m);
    }
    rm[tid] = m; rs[tid] = s;
    __syncthreads();
    for (int st = 512; st; st >>= 1) {
        if (tid < st) {
            float m1 = rm[tid], s1 = rs[tid], m2 = rm[tid + st], s2 = rs[tid + st];
            float M = fmaxf(m1, m2);
            rm[tid] = M;
            rs[tid] = s1 * __expf(m1 - M) + s2 * __expf(m2 - M);
        }
        __syncthreads();
    }
    if (tid == 0) { g_rowm[b] = rm[0]; g_rows[b] = rs[0]; }
}

// ---- final: grid (196, 128) x 256 ----
__global__ void k_final(float* __restrict__ out) {
    int b = blockIdx.y, v = blockIdx.x * 256 + threadIdx.x;
    if (v >= VTOT) return;
    float pg = g_pgen[b];
    float pv = (v < VT_) ? __expf(g_logits[(size_t)b * NPAD + v] - g_rowm[b]) / g_rows[b] : 0.f;
    float pc = g_copy[(size_t)b * VTOT + v];
    out[(size_t)b * VTOT + v] = logf(fmaxf(pg * pv + (1.f - pg) * pc, 1e-10f));
}

extern "C" void kernel_launch(void* const* d_in, const int* in_sizes, int n_in,
                              void* d_out, int out_size) {
    const int*   ids    = (const int*)d_in[0];
    const float* h0     = (const float*)d_in[1];
    const float* c0     = (const float*)d_in[2];
    const float* enc    = (const float*)d_in[3];
    const float* cenc   = (const float*)d_in[4];
    const int*   ci     = (const int*)d_in[5];
    const float* emb    = (const float*)d_in[6];
    const float* W_ih   = (const float*)d_in[7];
    const float* W_hh   = (const float*)d_in[8];
    const float* b_ih   = (const float*)d_in[9];
    const float* b_hh   = (const float*)d_in[10];
    const float* attn_W = (const float*)d_in[11];
    const float* attn_b = (const float*)d_in[12];
    const float* cattn_W = (const float*)d_in[13];
    const float* cattn_b = (const float*)d_in[14];
    const float* gen_W  = (const float*)d_in[15];
    const float* gen_b  = (const float*)d_in[16];
    const float* sig_b  = (const float*)d_in[17];
    const float* out_W  = (const float*)d_in[18];
    const float* out_b  = (const float*)d_in[19];
    float* out = (float*)d_out;

    k_embed<<<128, 768>>>(ids, emb, h0);                        // 1
    k_gates<<<128, 256>>>(W_ih, W_hh);                          // 2
    k_lstm<<<128, 512>>>(b_ih, b_hh, c0, out);                  // 3
    k_dproj<<<dim3(32, 2), 256>>>(attn_W, attn_b, cattn_W, cattn_b); // 4
    k_zero<<<6257, 256>>>();                                    // 5
    k_attn<<<1024, 256>>>(enc, cenc);                           // 6  <- ncu -s 5 captures this
    k_combine<<<256, 512>>>();                                  // 7
    k_pgen<<<128, 256>>>(gen_W, gen_b, sig_b, ci);              // 8
    k_scatter<<<512, 256>>>(ci);                                // 9
    k_proj<<<NT, 256>>>(out_W, out_b);                          // 10
    k_rowstat<<<128, 1024>>>();                                 // 11
    k_final<<<dim3(196, 128), 256>>>(out);                      // 12
}

// round 9
// speedup vs baseline: 1.5303x; 1.0071x over previous
#include <cuda_runtime.h>
#include <cuda_bf16.h>
#include <mma.h>
#include <cstdint>

using namespace nvcuda;

#define DINL __device__ __forceinline__
constexpr int B_ = 128, L_ = 4, VT_ = 50000, E_ = 256, H_ = 512, OOV_ = 50;
constexpr int VTOT = VT_ + OOV_, NPAD = 50048, NT = 782;

__device__ float g_xh[B_ * 768];
__device__ float g_gates[B_ * 2048];
__device__ float g_dec[B_ * H_];
__device__ __nv_bfloat16 g_dec_bf[B_ * H_];
__device__ float g_d1[B_ * H_], g_d2[B_ * H_];
__device__ float g_part_acc[1024 * H_], g_part_m[1024], g_part_s[1024];
__device__ float g_scores2[B_ * 1024], g_m2[B_], g_s2[B_];
__device__ float g_ctx[B_ * H_], g_cctx[B_ * H_], g_pgen[B_];
__device__ float g_logits[(size_t)B_ * NPAD];
__device__ float g_rowm[B_], g_rows[B_];
__device__ float g_copy[(size_t)B_ * VTOT];

DINL float sigf(float x) { return 1.0f / (1.0f + __expf(-x)); }

// ---- embed + pack [x|h0] : 128 blocks x 768 ----
__global__ void k_embed(const int* __restrict__ ids, const float* __restrict__ emb,
                        const float* __restrict__ h0) {
    int b = blockIdx.x, t = threadIdx.x;
    if (t < 256) {
        float s = 0.f;
        #pragma unroll
        for (int l = 0; l < L_; l++) s += emb[(size_t)ids[b * L_ + l] * E_ + t];
        g_xh[b * 768 + t] = tanhf(s * 0.25f);
    } else g_xh[b * 768 + t] = h0[b * H_ + t - 256];
}

// ---- fused gates GEMM: g_gates[128,2048] = xh[128,768] @ [W_ih|W_hh]^T. grid=128 ----
__global__ void k_gates(const float* __restrict__ W_ih, const float* __restrict__ W_hh) {
    __shared__ float As[128][33], Ws[16][33];
    int tid = threadIdx.x, j0 = blockIdx.x * 16, tx = tid & 7, ty = tid >> 3;
    float acc[4][2] = {};
    for (int k0 = 0; k0 < 768; k0 += 32) {
        #pragma unroll
        for (int i = 0; i < 16; i++) {
            int f = tid + i * 256;
            As[f >> 5][f & 31] = g_xh[(f >> 5) * 768 + k0 + (f & 31)];
        }
        #pragma unroll
        for (int i = 0; i < 2; i++) {
            int f = tid + i * 256, jj = j0 + (f >> 5), kk = k0 + (f & 31);
            Ws[f >> 5][f & 31] = (kk < 256) ? W_ih[jj * 256 + kk] : W_hh[jj * 512 + kk - 256];
        }
        __syncthreads();
        #pragma unroll
        for (int kk = 0; kk < 32; kk++) {
            float w0 = Ws[tx * 2][kk], w1 = Ws[tx * 2 + 1][kk];
            #pragma unroll
            for (int i = 0; i < 4; i++) {
                float a = As[ty * 4 + i][kk];
                acc[i][0] += a * w0; acc[i][1] += a * w1;
            }
        }
        __syncthreads();
    }
    #pragma unroll
    for (int i = 0; i < 4; i++)
        #pragma unroll
        for (int j = 0; j < 2; j++)
            g_gates[(ty * 4 + i) * 2048 + j0 + tx * 2 + j] = acc[i][j];
}

// ---- d1/d2 projections: grid (32,2) ----
__global__ void k_dproj(const float* __restrict__ attn_W, const float* __restrict__ attn_b,
                        const float* __restrict__ cattn_W, const float* __restrict__ cattn_b) {
    const float* W = blockIdx.y ? cattn_W : attn_W;
    const float* bias = blockIdx.y ? cattn_b : attn_b;
    float* C = blockIdx.y ? g_d2 : g_d1;
    __shared__ float As[128][33], Ws[16][33];
    int tid = threadIdx.x, j0 = blockIdx.x * 16, tx = tid & 7, ty = tid >> 3;
    float acc[4][2] = {};
    for (int k0 = 0; k0 < 512; k0 += 32) {
        #pragma unroll
        for (int i = 0; i < 16; i++) {
            int f = tid + i * 256;
            As[f >> 5][f & 31] = g_dec[(f >> 5) * 512 + k0 + (f & 31)];
        }
        #pragma unroll
        for (int i = 0; i < 2; i++) {
            int f = tid + i * 256;
            Ws[f >> 5][f & 31] = W[(j0 + (f >> 5)) * 512 + k0 + (f & 31)];
        }
        __syncthreads();
        #pragma unroll
        for (int kk = 0; kk < 32; kk++) {
            float w0 = Ws[tx * 2][kk], w1 = Ws[tx * 2 + 1][kk];
            #pragma unroll
            for (int i = 0; i < 4; i++) {
                float a = As[ty * 4 + i][kk];
                acc[i][0] += a * w0; acc[i][1] += a * w1;
            }
        }
        __syncthreads();
    }
    #pragma unroll
    for (int i = 0; i < 4; i++)
        #pragma unroll
        for (int j = 0; j < 2; j++) {
            int jj = j0 + tx * 2 + j;
            C[(ty * 4 + i) * 512 + jj] = acc[i][j] + bias[jj];
        }
}

// ---- LSTM epilogue: 128 x 512 ----
__global__ void k_lstm(const float* __restrict__ b_ih, const float* __restrict__ b_hh,
                       const float* __restrict__ c0, float* __restrict__ out) {
    int b = blockIdx.x, j = threadIdx.x;
    const float* gr = g_gates + b * 2048;
    float gi = gr[j] + b_ih[j] + b_hh[j];
    float gf = gr[j + 512] + b_ih[j + 512] + b_hh[j + 512];
    float gg = gr[j + 1024] + b_ih[j + 1024] + b_hh[j + 1024];
    float go = gr[j + 1536] + b_ih[j + 1536] + b_hh[j + 1536];
    float c = sigf(gf) * c0[b * H_ + j] + sigf(gi) * tanhf(gg);
    float h = sigf(go) * tanhf(c);
    g_dec[b * H_ + j] = h;
    g_dec_bf[b * H_ + j] = __float2bfloat16(h);
    out[(size_t)B_ * VTOT + b * H_ + j] = h;
    out[(size_t)B_ * VTOT + B_ * H_ + b * H_ + j] = c;
}

// ---- attention: per-warp independent online softmax, all-register mainloop ----
// grid 1024 = ((attn*128+b)*4+seg), 256 thr. Warp w owns rows {2w,2w+1} of each 16-row tile.
__global__ void __launch_bounds__(256) k_attn(const float* __restrict__ enc1,
                                              const float* __restrict__ enc2) {
    __shared__ float s_acc[8][512];
    __shared__ float s_m[8], s_s[8];
    int cta = blockIdx.x, seg = cta & 3, row = cta >> 2, attn = row >> 7, b = row & 127;
    const float* enc = (attn ? enc2 : enc1) + (size_t)b * 1024 * 512;
    const float* dv = (attn ? g_d2 : g_d1) + b * 512;
    int tid = threadIdx.x, wid = tid >> 5, lane = tid & 31;
    float4 d4[4];
    #pragma unroll
    for (int k = 0; k < 4; k++) d4[k] = ((const float4*)dv)[lane + 32 * k];
    float m = -1e30f, s = 0.f;
    float4 a4[4] = {};
    for (int tile = 0; tile < 16; tile++) {
        int r0 = seg * 256 + tile * 16 + 2 * wid;
        const float4* p0 = (const float4*)(enc + (size_t)r0 * 512);
        float4 v0[4], v1[4];
        #pragma unroll
        for (int k = 0; k < 4; k++) { v0[k] = p0[lane + 32 * k]; v1[k] = p0[128 + lane + 32 * k]; }
        float dot0 = 0.f, dot1 = 0.f;
        #pragma unroll
        for (int k = 0; k < 4; k++) {
            dot0 += v0[k].x * d4[k].x + v0[k].y * d4[k].y + v0[k].z * d4[k].z + v0[k].w * d4[k].w;
            dot1 += v1[k].x * d4[k].x + v1[k].y * d4[k].y + v1[k].z * d4[k].z + v1[k].w * d4[k].w;
        }
        #pragma unroll
        for (int off = 16; off; off >>= 1) {
            dot0 += __shfl_xor_sync(0xFFFFFFFFu, dot0, off);
            dot1 += __shfl_xor_sync(0xFFFFFFFFu, dot1, off);
        }
        if (attn && lane == 0) {
            g_scores2[b * 1024 + r0] = dot0;
            g_scores2[b * 1024 + r0 + 1] = dot1;
        }
        float nm = fmaxf(m, fmaxf(dot0, dot1));
        float sc = __expf(m - nm);
        float p0e = __expf(dot0 - nm), p1e = __expf(dot1 - nm);
        s = s * sc + p0e + p1e;
        #pragma unroll
        for (int k = 0; k < 4; k++) {
            a4[k].x = a4[k].x * sc + p0e * v0[k].x + p1e * v1[k].x;
            a4[k].y = a4[k].y * sc + p0e * v0[k].y + p1e * v1[k].y;
            a4[k].z = a4[k].z * sc + p0e * v0[k].z + p1e * v1[k].z;
            a4[k].w = a4[k].w * sc + p0e * v0[k].w + p1e * v1[k].w;
        }
        m = nm;
    }
    #pragma unroll
    for (int k = 0; k < 4; k++) ((float4*)s_acc[wid])[lane + 32 * k] = a4[k];
    if (lane == 0) { s_m[wid] = m; s_s[wid] = s; }
    __syncthreads();
    float M = s_m[0];
    #pragma unroll
    for (int w = 1; w < 8; w++) M = fmaxf(M, s_m[w]);
    float S = 0.f, acc0 = 0.f, acc1 = 0.f;
    #pragma unroll
    for (int w = 0; w < 8; w++) {
        float f = __expf(s_m[w] - M);
        S += f * s_s[w];
        acc0 += f * s_acc[w][tid];
        acc1 += f * s_acc[w][tid + 256];
    }
    float* pa = g_part_acc + (size_t)cta * 512;
    pa[tid] = acc0; pa[tid + 256] = acc1;
    if (tid == 0) { g_part_m[cta] = M; g_part_s[cta] = S; }
}

// ---- combine 4 segments: 256 x 512 ----
__global__ void k_combine() {
    int row = blockIdx.x, h = threadIdx.x;
    float m0 = g_part_m[row * 4], m1 = g_part_m[row * 4 + 1];
    float m2 = g_part_m[row * 4 + 2], m3 = g_part_m[row * 4 + 3];
    float M = fmaxf(fmaxf(m0, m1), fmaxf(m2, m3));
    float w0 = __expf(m0 - M), w1 = __expf(m1 - M), w2 = __expf(m2 - M), w3 = __expf(m3 - M);
    float S = g_part_s[row * 4] * w0 + g_part_s[row * 4 + 1] * w1 +
              g_part_s[row * 4 + 2] * w2 + g_part_s[row * 4 + 3] * w3;
    float a = g_part_acc[(size_t)(row * 4) * 512 + h] * w0 +
              g_part_acc[(size_t)(row * 4 + 1) * 512 + h] * w1 +
              g_part_acc[(size_t)(row * 4 + 2) * 512 + h] * w2 +
              g_part_acc[(size_t)(row * 4 + 3) * 512 + h] * w3;
    float v = a / S;
    if (row < 128) g_ctx[row * 512 + h] = v;
    else {
        g_cctx[(row - 128) * 512 + h] = v;
        if (h == 0) { g_m2[row - 128] = M; g_s2[row - 128] = S; }
    }
}

// ---- p_gen: 128 x 256 ----
__global__ void k_pgen(const float* __restrict__ gen_W, const float* __restrict__ gen_b,
                       const float* __restrict__ sig_b, const int* __restrict__ ci) {
    __shared__ float red[256];
    __shared__ int redc[256];
    int b = blockIdx.x, tid = threadIdx.x;
    float part = 0.f;
    for (int i = tid; i < 1792; i += 256) {
        float fv;
        if (i < 512) fv = g_ctx[b * 512 + i];
        else if (i < 1024) fv = g_cctx[b * 512 + i - 512];
        else if (i < 1536) fv = g_dec[b * 512 + i - 1024];
        else fv = g_xh[b * 768 + i - 1536];
        part += fv * gen_W[i];
    }
    int cnt = 0;
    for (int t = tid; t < 1024; t += 256) cnt += (ci[b * 1024 + t] > 0);
    red[tid] = part; redc[tid] = cnt;
    __syncthreads();
    for (int st = 128; st; st >>= 1) {
        if (tid < st) { red[tid] += red[tid + st]; redc[tid] += redc[tid + st]; }
        __syncthreads();
    }
    if (tid == 0) g_pgen[b] = (redc[0] == 0) ? 1.0f : sigf(red[0] + gen_b[0] + sig_b[0]);
}

__global__ void k_zero() {
    size_t i = (size_t)blockIdx.x * 256 + threadIdx.x;
    if (i < ((size_t)B_ * VTOT) / 4) ((float4*)g_copy)[i] = make_float4(0.f, 0.f, 0.f, 0.f);
}

__global__ void k_scatter(const int* __restrict__ ci) {
    int idx = blockIdx.x * 256 + threadIdx.x;
    int b = idx >> 10, t = idx & 1023;
    float p = __expf(g_scores2[b * 1024 + t] - g_m2[b]) / g_s2[b];
    atomicAdd(&g_copy[(size_t)b * VTOT + ci[b * 1024 + t]], p);
}

// ---- vocab projection: wmma bf16, 128x64 per CTA, padded smem (stride 72). 782 x 256 ----
__global__ void __launch_bounds__(256) k_proj(const float* __restrict__ out_W,
                                              const float* __restrict__ out_b) {
    __shared__ __align__(16) __nv_bfloat16 As[128][72];   // 18 KB, rows staggered 4 banks
    __shared__ __align__(16) __nv_bfloat16 Bs[64][72];    //  9 KB
    __shared__ __align__(16) float BiasS[16][64];         //  4 KB
    int tid = threadIdx.x, wid = tid >> 5;
    int v0 = blockIdx.x * 64;
    int wr = wid >> 1, wc = wid & 1;
    {
        int c = tid & 63, r4 = tid >> 6;
        int v = v0 + c;
        float bv = (v < VT_) ? out_b[v] : 0.f;
        #pragma unroll
        for (int rr = 0; rr < 4; rr++) BiasS[r4 * 4 + rr][c] = bv;
    }
    __syncthreads();
    wmma::fragment<wmma::accumulator, 16, 16, 16, float> c_frag[2][2];
    #pragma unroll
    for (int i = 0; i < 2; i++)
        #pragma unroll
        for (int j = 0; j < 2; j++)
            wmma::load_matrix_sync(c_frag[i][j], &BiasS[0][wc * 32 + j * 16], 64,
                                   wmma::mem_row_major);
    const uint32_t* decw = (const uint32_t*)g_dec_bf;
    for (int kc = 0; kc < 8; kc++) {
        #pragma unroll
        for (int i = 0; i < 16; i++) {
            int f = tid + i * 256, r = f >> 5, c = f & 31;
            ((uint32_t*)&As[r][0])[c] = decw[r * 256 + kc * 32 + c];
        }
        #pragma unroll
        for (int i = 0; i < 8; i++) {
            int f = tid + i * 256, r = f >> 5, c = f & 31;
            int v = v0 + r;
            float2 w2 = (v < VT_) ? ((const float2*)(out_W + (size_t)v * 512 + kc * 64))[c]
                                  : make_float2(0.f, 0.f);
            __nv_bfloat162 bb = __floats2bfloat162_rn(w2.x, w2.y);
            ((uint32_t*)&Bs[r][0])[c] = *(uint32_t*)&bb;
        }
        __syncthreads();
        #pragma unroll
        for (int kk = 0; kk < 64; kk += 16) {
            wmma::fragment<wmma::matrix_a, 16, 16, 16, __nv_bfloat16, wmma::row_major> a_frag[2];
            wmma::fragment<wmma::matrix_b, 16, 16, 16, __nv_bfloat16, wmma::col_major> b_frag[2];
            #pragma unroll
            for (int i = 0; i < 2; i++)
                wmma::load_matrix_sync(a_frag[i], &As[wr * 32 + i * 16][kk], 72);
            #pragma unroll
            for (int j = 0; j < 2; j++)
                wmma::load_matrix_sync(b_frag[j], &Bs[wc * 32 + j * 16][kk], 72);
            #pragma unroll
            for (int i = 0; i < 2; i++)
                #pragma unroll
                for (int j = 0; j < 2; j++)
                    wmma::mma_sync(c_frag[i][j], a_frag[i], b_frag[j], c_frag[i][j]);
        }
        __syncthreads();
    }
    #pragma unroll
    for (int i = 0; i < 2; i++)
        #pragma unroll
        for (int j = 0; j < 2; j++)
            wmma::store_matrix_sync(
                g_logits + (size_t)(wr * 32 + i * 16) * NPAD + v0 + wc * 32 + j * 16,
                c_frag[i][j], NPAD, wmma::mem_row_major);
}

// ---- row softmax stats: 128 x 1024 ----
__global__ void k_rowstat() {
    __shared__ float rm[1024], rs[1024];
    int b = blockIdx.x, tid = threadIdx.x;
    float m = -1e30f, s = 0.f;
    for (int v = tid; v < VT_; v += 1024) {
        float x = g_logits[(size_t)b * NPAD + v];
        if (x > m) { s = s * __expf(m - x) + 1.f; m = x; }
        else s += __expf(x - m);
    }
    rm[tid] = m; rs[tid] = s;
    __syncthreads();
    for (int st = 512; st; st >>= 1) {
        if (tid < st) {
            float m1 = rm[tid], s1 = rs[tid], m2 = rm[tid + st], s2 = rs[tid + st];
            float M = fmaxf(m1, m2);
            rm[tid] = M;
            rs[tid] = s1 * __expf(m1 - M) + s2 * __expf(m2 - M);
        }
        __syncthreads();
    }
    if (tid == 0) { g_rowm[b] = rm[0]; g_rows[b] = rs[0]; }
}

// ---- final: grid (196, 128) x 256 ----
__global__ void k_final(float* __restrict__ out) {
    int b = blockIdx.y, v = blockIdx.x * 256 + threadIdx.x;
    if (v >= VTOT) return;
    float pg = g_pgen[b];
    float pv = (v < VT_) ? __expf(g_logits[(size_t)b * NPAD + v] - g_rowm[b]) / g_rows[b] : 0.f;
    float pc = g_copy[(size_t)b * VTOT + v];
    out[(size_t)b * VTOT + v] = logf(fmaxf(pg * pv + (1.f - pg) * pc, 1e-10f));
}

extern "C" void kernel_launch(void* const* d_in, const int* in_sizes, int n_in,
                              void* d_out, int out_size) {
    const int*   ids    = (const int*)d_in[0];
    const float* h0     = (const float*)d_in[1];
    const float* c0     = (const float*)d_in[2];
    const float* enc    = (const float*)d_in[3];
    const float* cenc   = (const float*)d_in[4];
    const int*   ci     = (const int*)d_in[5];
    const float* emb    = (const float*)d_in[6];
    const float* W_ih   = (const float*)d_in[7];
    const float* W_hh   = (const float*)d_in[8];
    const float* b_ih   = (const float*)d_in[9];
    const float* b_hh   = (const float*)d_in[10];
    const float* attn_W = (const float*)d_in[11];
    const float* attn_b = (const float*)d_in[12];
    const float* cattn_W = (const float*)d_in[13];
    const float* cattn_b = (const float*)d_in[14];
    const float* gen_W  = (const float*)d_in[15];
    const float* gen_b  = (const float*)d_in[16];
    const float* sig_b  = (const float*)d_in[17];
    const float* out_W  = (const float*)d_in[18];
    const float* out_b  = (const float*)d_in[19];
    float* out = (float*)d_out;

    k_embed<<<128, 768>>>(ids, emb, h0);                        // 1
    k_gates<<<128, 256>>>(W_ih, W_hh);                          // 2
    k_lstm<<<128, 512>>>(b_ih, b_hh, c0, out);                  // 3
    k_dproj<<<dim3(32, 2), 256>>>(attn_W, attn_b, cattn_W, cattn_b); // 4
    k_zero<<<6257, 256>>>();                                    // 5
    k_attn<<<1024, 256>>>(enc, cenc);                           // 6  <- ncu -s 5 captures this
    k_combine<<<256, 512>>>();                                  // 7
    k_pgen<<<128, 256>>>(gen_W, gen_b, sig_b, ci);              // 8
    k_scatter<<<512, 256>>>(ci);                                // 9
    k_proj<<<NT, 256>>>(out_W, out_b);                          // 10
    k_rowstat<<<128, 1024>>>();                                 // 11
    k_final<<<dim3(196, 128), 256>>>(out);                      // 12
}